// round 4
// baseline (speedup 1.0000x reference)
#include <cuda_runtime.h>
#include <math.h>

#define PP 32
#define VV 200
#define FF 5
#define TT 16
#define RR 5
#define GG 80
#define KK 16
#define BBATCH 16
#define NLL 7
#define EPSF 1e-5f
#define XROW 51200
#define BIGLEN 32000
#define LOG2E 1.44269504088896340736f

// scratch
__device__ float g_h[BBATCH * PP * GG];        // h activations (B,P,G)
__device__ float g_p2[BBATCH * 8 * 64];        // W2 partial sums (B, slice, 64)

// ---- packed fp32x2 helpers (Blackwell FFMA2 path) ----
__device__ __forceinline__ unsigned long long pk2(float a, float b) {
    unsigned long long r;
    asm("mov.b64 %0, {%1,%2};" : "=l"(r) : "f"(a), "f"(b));
    return r;
}
__device__ __forceinline__ void f2fma(unsigned long long& d, unsigned long long a,
                                      unsigned long long b) {
    asm("fma.rn.f32x2 %0, %1, %2, %0;" : "+l"(d) : "l"(a), "l"(b));
}
__device__ __forceinline__ unsigned long long f2mul(unsigned long long a,
                                                    unsigned long long b) {
    unsigned long long r;
    asm("mul.rn.f32x2 %0, %1, %2;" : "=l"(r) : "l"(a), "l"(b));
    return r;
}
__device__ __forceinline__ float f2sum(unsigned long long a) {
    float x, y;
    asm("mov.b64 {%0,%1}, %2;" : "=f"(x), "=f"(y) : "l"(a));
    return x + y;
}
__device__ __forceinline__ float ex2f(float x) {
    float y;
    asm("ex2.approx.f32 %0, %1;" : "=f"(y) : "f"(x));
    return y;
}
__device__ __forceinline__ unsigned long long lds2(const float* p) {
    return *(const unsigned long long*)p;   // 8B-aligned by construction
}

// dynamic smem layout (floats):
#define OFF_W    0                      // s_w   [KK][VV]  3200  pre-wrapped theta
#define OFF_C    (OFF_W + KK * VV)      // s_c   [RR][VV]  1000
#define OFF_F    (OFF_C + RR * VV)      // s_feat[FF][VV]  1000
#define OFF_DESC (OFF_F + FF * VV)      // s_desc[KK][400] 6400
#define OFF_CONV (OFF_DESC + KK * FF * GG)  // 400
#define OFF_PMAX (OFF_CONV + FF * GG)       // 1200
#define OFF_HP   (OFF_PMAX + 3 * FF * GG)   // 240
#define OFF_MUT  (OFF_HP + 3 * GG)          // 16
#define OFF_INVT (OFF_MUT + TT)             // 16
#define SMEM_FLOATS (OFF_INVT + TT)         // 13472 -> 53888 B

// ---------------------------------------------------------------------------
// Kernel 1: one CTA per (b,p). desc -> conv(max over K rotations) -> W1 -> g_h
// ---------------------------------------------------------------------------
__global__ void __launch_bounds__(256, 2)
masif_k1(const float* __restrict__ x,
         const float* __restrict__ mu_rho,
         const float* __restrict__ sigma_rho,
         const float* __restrict__ mu_theta,
         const float* __restrict__ sigma_theta,
         const float* __restrict__ W_conv,
         const float* __restrict__ b_conv,
         const float* __restrict__ W1,
         const float* __restrict__ b1)
{
    extern __shared__ float sm[];
    float* s_w    = sm + OFF_W;
    float* s_c    = sm + OFF_C;
    float* s_feat = sm + OFF_F;
    float* s_desc = sm + OFF_DESC;
    float* s_conv = sm + OFF_CONV;
    float* s_pmax = sm + OFF_PMAX;
    float* s_hp   = sm + OFF_HP;
    float* s_mut  = sm + OFF_MUT;
    float* s_invt = sm + OFF_INVT;

    const int tid = threadIdx.x;
    const int bp  = blockIdx.x;
    const int b   = bp / PP;
    const int p   = bp % PP;

    const float* xb    = x + (size_t)b * XROW;
    const float* rhop  = xb + BIGLEN + 0 * PP * VV + p * VV;
    const float* thp   = xb + BIGLEN + 1 * PP * VV + p * VV;
    const float* maskp = xb + BIGLEN + 2 * PP * VV + p * VV;
    const float* featp = xb + p * VV * FF;

    const float TWO_PI = 6.28318530717958647692f;
    const float OFF_STEP = (float)(2.0 * M_PI / 16.0);

    if (tid < TT) {
        s_mut[tid] = mu_theta[tid];
        float st = sigma_theta[tid];
        s_invt[tid] = LOG2E / (st * st + EPSF);
    }

    // Phase A: rho gaussians, feature transpose, PRE-WRAPPED rotated thetas
    if (tid < VV) {
        int v = tid;
        float rv = rhop[v];
        float mv = maskp[v];
        float th = thp[v];
#pragma unroll
        for (int f = 0; f < FF; ++f)
            s_feat[f * VV + v] = featp[v * FF + f];
#pragma unroll
        for (int r = 0; r < RR; ++r) {
            float mr = mu_rho[r * TT];      // depends only on r
            float sr = sigma_rho[r * TT];
            float d = rv - mr;
            s_c[r * VV + v] = ex2f(-(d * d) * (LOG2E / (sr * sr + EPSF))) * mv;
        }
#pragma unroll
        for (int k = 0; k < KK; ++k) {
            float u = th + OFF_STEP * (float)k;
            if (u >= TWO_PI) u -= TWO_PI;
            s_w[k * VV + v] = u;
        }
    }
    __syncthreads();

    // Phase B: thread (k,t): acc[f][r] = sum_v a(v)*c(r,v)*feat(f,v), den[r]=sum a*c
    // a = ex2(alpha*u^2 + beta*u + gamma) with u pre-wrapped.
    {
        const int k = tid >> 4;
        const int t = tid & 15;
        const float mut   = s_mut[t];
        const float invt  = s_invt[t];
        const float alpha = -invt;
        const float beta  = 2.0f * invt * mut;
        const float gamma = -invt * mut * mut;
        const float* wk = s_w + k * VV;

        unsigned long long acc[FF * RR];   // acc[f*5+r]
        unsigned long long den[RR];
#pragma unroll
        for (int i = 0; i < FF * RR; ++i) acc[i] = 0ull;
#pragma unroll
        for (int r = 0; r < RR; ++r) den[r] = 0ull;

#pragma unroll 2
        for (int v = 0; v < VV; v += 2) {
            float2 u2 = *(const float2*)(wk + v);
            float a0 = ex2f(fmaf(fmaf(alpha, u2.x, beta), u2.x, gamma));
            float a1 = ex2f(fmaf(fmaf(alpha, u2.y, beta), u2.y, gamma));
            unsigned long long A = pk2(a0, a1);

            unsigned long long Q[RR];
#pragma unroll
            for (int r = 0; r < RR; ++r) {
                unsigned long long C = lds2(s_c + r * VV + v);
                f2fma(den[r], A, C);
                Q[r] = f2mul(A, C);
            }
#pragma unroll
            for (int f = 0; f < FF; ++f) {
                unsigned long long Fp = lds2(s_feat + f * VV + v);
#pragma unroll
                for (int r = 0; r < RR; ++r)
                    f2fma(acc[f * RR + r], Q[r], Fp);
            }
        }
#pragma unroll
        for (int r = 0; r < RR; ++r) {
            float inv = 1.0f / (f2sum(den[r]) + EPSF);
#pragma unroll
            for (int f = 0; f < FF; ++f)
                s_desc[k * (FF * GG) + f * GG + r * TT + t] = f2sum(acc[f * RR + r]) * inv;
        }
    }
    __syncthreads();

    // Phase C: conv(f,h) = max_k sum_g desc_k(f,g)*Wc(f,g,h)
    if (tid < 240) {
        const int h  = tid % GG;
        const int kg = tid / GG;           // 0,1,2
        const int kbase = kg * 6;
        const int nk = (kg == 2) ? 4 : 6;
#pragma unroll 1
        for (int f = 0; f < FF; ++f) {
            unsigned long long a2[6];
#pragma unroll
            for (int j = 0; j < 6; ++j) a2[j] = 0ull;
            const float* Wf = W_conv + f * GG * GG + h;
            for (int g = 0; g < GG; g += 2) {
                float w0 = __ldg(Wf + g * GG);
                float w1 = __ldg(Wf + (g + 1) * GG);
                unsigned long long Wp = pk2(w0, w1);
#pragma unroll
                for (int j = 0; j < 6; ++j) {
                    if (j < nk) {
                        unsigned long long Dp = lds2(s_desc + (kbase + j) * (FF * GG) + f * GG + g);
                        f2fma(a2[j], Dp, Wp);
                    }
                }
            }
            float m = -INFINITY;
#pragma unroll
            for (int j = 0; j < 6; ++j)
                if (j < nk) m = fmaxf(m, f2sum(a2[j]));
            s_pmax[kg * (FF * GG) + f * GG + h] = m;
        }
    }
    __syncthreads();
    for (int i = tid; i < FF * GG; i += 256) {
        float m = fmaxf(fmaxf(s_pmax[i], s_pmax[FF * GG + i]), s_pmax[2 * FF * GG + i]);
        s_conv[i] = fmaxf(m + b_conv[i], 0.0f);
    }
    __syncthreads();

    // Phase D: h(j) = relu(sum_i conv(i)*W1[i][j] + b1[j])
    if (tid < 240) {
        int j = tid % GG;
        int part = tid / GG;
        int i0 = part * 134;
        int i1 = (i0 + 134 < 400) ? (i0 + 134) : 400;
        float s = 0.0f;
        for (int i = i0; i < i1; ++i)
            s = fmaf(s_conv[i], __ldg(W1 + i * GG + j), s);
        s_hp[part * GG + j] = s;
    }
    __syncthreads();
    if (tid < GG) {
        float hv = s_hp[tid] + s_hp[GG + tid] + s_hp[2 * GG + tid] + b1[tid];
        g_h[bp * GG + tid] = fmaxf(hv, 0.0f);
    }
}

// ---------------------------------------------------------------------------
// Kernel 2a: grid (slice s=0..7, batch b). cov slice (10 rows) + W2 partial.
// ---------------------------------------------------------------------------
__global__ void __launch_bounds__(256, 4)
masif_k2a(const float* __restrict__ W2)
{
    __shared__ float s_h[PP][GG];
    __shared__ float s_cov[800];
    __shared__ float s_red[4][64];

    const int tid = threadIdx.x;
    const int s = blockIdx.x;
    const int b = blockIdx.y;

    for (int i = tid; i < PP * GG; i += 256)
        s_h[i / GG][i % GG] = g_h[b * PP * GG + i];
    __syncthreads();

    for (int idx = tid; idx < 800; idx += 256) {
        int i1 = s * 10 + idx / GG;
        int i2 = idx % GG;
        float acc = 0.0f;
#pragma unroll
        for (int pp = 0; pp < PP; ++pp)
            acc = fmaf(s_h[pp][i1], s_h[pp][i2], acc);
        s_cov[idx] = acc * (1.0f / 32.0f);
    }
    __syncthreads();

    {
        const int j = tid % 64;
        const int part = tid / 64;
        const float* W2s = W2 + ((size_t)s * 800 + part * 200) * 64 + j;
        const float* cv = s_cov + part * 200;
        float a0 = 0.f, a1 = 0.f, a2 = 0.f, a3 = 0.f;
#pragma unroll 4
        for (int i = 0; i < 200; i += 4) {
            a0 = fmaf(cv[i + 0], __ldg(W2s + (size_t)(i + 0) * 64), a0);
            a1 = fmaf(cv[i + 1], __ldg(W2s + (size_t)(i + 1) * 64), a1);
            a2 = fmaf(cv[i + 2], __ldg(W2s + (size_t)(i + 2) * 64), a2);
            a3 = fmaf(cv[i + 3], __ldg(W2s + (size_t)(i + 3) * 64), a3);
        }
        s_red[part][j] = (a0 + a1) + (a2 + a3);
    }
    __syncthreads();
    if (tid < 64)
        g_p2[(b * 8 + s) * 64 + tid] =
            s_red[0][tid] + s_red[1][tid] + s_red[2][tid] + s_red[3][tid];
}

// ---------------------------------------------------------------------------
// Kernel 2b: one CTA per batch. reduce partials + relu + W3 + softmax.
// ---------------------------------------------------------------------------
__global__ void __launch_bounds__(64, 8)
masif_k2b(const float* __restrict__ b2,
          const float* __restrict__ W3, const float* __restrict__ b3,
          float* __restrict__ out)
{
    __shared__ float s_h2[64];
    __shared__ float s_logit[NLL];
    const int tid = threadIdx.x;
    const int b = blockIdx.x;

    {
        float v = b2[tid];
#pragma unroll
        for (int s = 0; s < 8; ++s)
            v += g_p2[(b * 8 + s) * 64 + tid];
        s_h2[tid] = fmaxf(v, 0.0f);
    }
    __syncthreads();
    if (tid < NLL) {
        float s = b3[tid];
#pragma unroll
        for (int j = 0; j < 64; ++j)
            s = fmaf(s_h2[j], W3[j * NLL + tid], s);
        s_logit[tid] = s;
    }
    __syncthreads();
    if (tid == 0) {
        float m = -INFINITY;
        for (int l = 0; l < NLL; ++l) m = fmaxf(m, s_logit[l]);
        float e[NLL];
        float sum = 0.0f;
        for (int l = 0; l < NLL; ++l) { e[l] = __expf(s_logit[l] - m); sum += e[l]; }
        float inv = 1.0f / sum;
        for (int l = 0; l < NLL; ++l) out[b * NLL + l] = e[l] * inv;
    }
}

extern "C" void kernel_launch(void* const* d_in, const int* in_sizes, int n_in,
                              void* d_out, int out_size)
{
    const float* x           = (const float*)d_in[0];
    const float* mu_rho      = (const float*)d_in[1];
    const float* sigma_rho   = (const float*)d_in[2];
    const float* mu_theta    = (const float*)d_in[3];
    const float* sigma_theta = (const float*)d_in[4];
    const float* W_conv      = (const float*)d_in[5];
    const float* b_conv      = (const float*)d_in[6];
    const float* W1          = (const float*)d_in[7];
    const float* b1          = (const float*)d_in[8];
    const float* W2          = (const float*)d_in[9];
    const float* b2          = (const float*)d_in[10];
    const float* W3          = (const float*)d_in[11];
    const float* b3          = (const float*)d_in[12];
    float* out = (float*)d_out;

    const int smem1 = SMEM_FLOATS * (int)sizeof(float);   // 53888 B
    cudaFuncSetAttribute(masif_k1, cudaFuncAttributeMaxDynamicSharedMemorySize, smem1);

    masif_k1<<<BBATCH * PP, 256, smem1>>>(x, mu_rho, sigma_rho, mu_theta, sigma_theta,
                                          W_conv, b_conv, W1, b1);
    masif_k2a<<<dim3(8, BBATCH), 256>>>(W2);
    masif_k2b<<<BBATCH, 64>>>(b2, W3, b3, out);
}

// round 5
// speedup vs baseline: 1.1012x; 1.1012x over previous
#include <cuda_runtime.h>
#include <math.h>

#define PP 32
#define VV 200
#define FF 5
#define TT 16
#define RR 5
#define GG 80
#define KK 16
#define BBATCH 16
#define NLL 7
#define EPSF 1e-5f
#define XROW 51200
#define BIGLEN 32000
#define LOG2E 1.44269504088896340736f

// scratch
__device__ float g_h[BBATCH * PP * GG];        // h activations (B,P,G)
__device__ float g_p2[BBATCH * 8 * 64];        // W2 partial sums (B, slice, 64)

// ---- packed fp32x2 helpers (Blackwell FFMA2 path) ----
__device__ __forceinline__ unsigned long long pk2(float a, float b) {
    unsigned long long r;
    asm("mov.b64 %0, {%1,%2};" : "=l"(r) : "f"(a), "f"(b));
    return r;
}
__device__ __forceinline__ void f2fma(unsigned long long& d, unsigned long long a,
                                      unsigned long long b) {
    asm("fma.rn.f32x2 %0, %1, %2, %0;" : "+l"(d) : "l"(a), "l"(b));
}
__device__ __forceinline__ unsigned long long f2mul(unsigned long long a,
                                                    unsigned long long b) {
    unsigned long long r;
    asm("mul.rn.f32x2 %0, %1, %2;" : "=l"(r) : "l"(a), "l"(b));
    return r;
}
__device__ __forceinline__ float f2sum(unsigned long long a) {
    float x, y;
    asm("mov.b64 {%0,%1}, %2;" : "=f"(x), "=f"(y) : "l"(a));
    return x + y;
}
__device__ __forceinline__ float ex2f(float x) {
    float y;
    asm("ex2.approx.f32 %0, %1;" : "=f"(y) : "f"(x));
    return y;
}
__device__ __forceinline__ unsigned long long lds2(const float* p) {
    return *(const unsigned long long*)p;   // 8B-aligned by construction
}

// ---------------------------------------------------------------------------
// Kernel 1: one CTA per (b,p). desc -> conv(max over K rotations) -> W1 -> g_h
// Phase A/B identical to the proven R2 kernel; Phase C/D get MLP unrolls.
// ---------------------------------------------------------------------------
__global__ void __launch_bounds__(256, 2)
masif_k1(const float* __restrict__ x,
         const float* __restrict__ mu_rho,
         const float* __restrict__ sigma_rho,
         const float* __restrict__ mu_theta,
         const float* __restrict__ sigma_theta,
         const float* __restrict__ W_conv,
         const float* __restrict__ b_conv,
         const float* __restrict__ W1,
         const float* __restrict__ b1)
{
    __shared__ float s_th[VV];            // raw theta
    __shared__ float s_c[RR][VV];         // rho gaussians * mask
    __shared__ float s_feat[FF][VV];      // transposed features
    __shared__ float s_mut[TT];
    __shared__ float s_invt[TT];          // LOG2E / (sigma_t^2 + eps)
    __shared__ float s_desc[KK][FF * GG]; // desc[k][f*80+g]
    __shared__ float s_conv[FF * GG];
    __shared__ float s_pmax[3][FF * GG];
    __shared__ float s_hp[3][GG];

    const int tid = threadIdx.x;
    const int bp  = blockIdx.x;
    const int b   = bp / PP;
    const int p   = bp % PP;

    const float* xb    = x + (size_t)b * XROW;
    const float* rhop  = xb + BIGLEN + 0 * PP * VV + p * VV;
    const float* thp   = xb + BIGLEN + 1 * PP * VV + p * VV;
    const float* maskp = xb + BIGLEN + 2 * PP * VV + p * VV;
    const float* featp = xb + p * VV * FF;

    const float TWO_PI = 6.28318530717958647692f;
    const float OFF_STEP = (float)(2.0 * M_PI / 16.0);

    if (tid < TT) {
        s_mut[tid] = mu_theta[tid];
        float st = sigma_theta[tid];
        s_invt[tid] = LOG2E / (st * st + EPSF);
    }

    // Phase A: rho gaussians, feature transpose, theta copy
    if (tid < VV) {
        int v = tid;
        float rv = rhop[v];
        float mv = maskp[v];
        s_th[v] = thp[v];
#pragma unroll
        for (int f = 0; f < FF; ++f)
            s_feat[f][v] = featp[v * FF + f];
#pragma unroll
        for (int r = 0; r < RR; ++r) {
            float mr = mu_rho[r * TT];      // depends only on r
            float sr = sigma_rho[r * TT];
            float d = rv - mr;
            float c = ex2f(-(d * d) * (LOG2E / (sr * sr + EPSF))) * mv;
            s_c[r][v] = c;
        }
    }
    __syncthreads();

    // Phase B: per thread (k,t): D(row) = sum_v a(v) * c(r,v) * feat(f,v)
    {
        const int k = tid >> 4;
        const int t = tid & 15;
        const float mut  = s_mut[t];
        const float invt = s_invt[t];
        const float offk = OFF_STEP * (float)k;

        unsigned long long acc[RR * FF];   // feat accumulators (pairs over v)
        unsigned long long accd[RR];       // denominator accumulators
#pragma unroll
        for (int i = 0; i < RR * FF; ++i) acc[i] = 0ull;
#pragma unroll
        for (int r = 0; r < RR; ++r) accd[r] = 0ull;

        for (int v = 0; v < VV; v += 2) {
            float2 th2 = *(const float2*)(s_th + v);
            float u0 = th2.x + offk; if (u0 >= TWO_PI) u0 -= TWO_PI;
            float u1 = th2.y + offk; if (u1 >= TWO_PI) u1 -= TWO_PI;
            float d0 = u0 - mut, d1 = u1 - mut;
            float a0 = ex2f(-(d0 * d0) * invt);
            float a1 = ex2f(-(d1 * d1) * invt);
            unsigned long long A = pk2(a0, a1);

            unsigned long long Fv[FF];
#pragma unroll
            for (int f = 0; f < FF; ++f) Fv[f] = lds2(&s_feat[f][v]);

#pragma unroll
            for (int r = 0; r < RR; ++r) {
                unsigned long long C = lds2(&s_c[r][v]);
                f2fma(accd[r], A, C);                  // denom += a*c
                unsigned long long Q = f2mul(A, C);
#pragma unroll
                for (int f = 0; f < FF; ++f)
                    f2fma(acc[r * FF + f], Q, Fv[f]);  // += (a*c)*feat
            }
        }
#pragma unroll
        for (int r = 0; r < RR; ++r) {
            float inv = 1.0f / (f2sum(accd[r]) + EPSF);
#pragma unroll
            for (int f = 0; f < FF; ++f)
                s_desc[k][f * GG + r * TT + t] = f2sum(acc[r * FF + f]) * inv;
        }
    }
    __syncthreads();

    // Phase C: conv(f,h) = max_k sum_g desc_k(f,g)*Wc(f,g,h)
    // g-loop unrolled x2 (step 4) so 4 independent LDGs are in flight.
    if (tid < 240) {
        const int h  = tid % GG;
        const int kg = tid / GG;           // 0,1,2 -> k ranges 0-5, 6-11, 12-15
        const int kbase = kg * 6;
        const int nk = (kg == 2) ? 4 : 6;
#pragma unroll 1
        for (int f = 0; f < FF; ++f) {
            unsigned long long a2[6];
#pragma unroll
            for (int j = 0; j < 6; ++j) a2[j] = 0ull;
            const float* Wf = W_conv + f * GG * GG + h;
            for (int g = 0; g < GG; g += 4) {
                float w0 = __ldg(Wf + (g + 0) * GG);
                float w1 = __ldg(Wf + (g + 1) * GG);
                float w2 = __ldg(Wf + (g + 2) * GG);
                float w3 = __ldg(Wf + (g + 3) * GG);
                unsigned long long Wp0 = pk2(w0, w1);
                unsigned long long Wp1 = pk2(w2, w3);
#pragma unroll
                for (int j = 0; j < 6; ++j) {
                    if (j < nk) {
                        unsigned long long Dp0 = lds2(&s_desc[kbase + j][f * GG + g]);
                        unsigned long long Dp1 = lds2(&s_desc[kbase + j][f * GG + g + 2]);
                        f2fma(a2[j], Dp0, Wp0);
                        f2fma(a2[j], Dp1, Wp1);
                    }
                }
            }
            float m = -INFINITY;
#pragma unroll
            for (int j = 0; j < 6; ++j)
                if (j < nk) m = fmaxf(m, f2sum(a2[j]));
            s_pmax[kg][f * GG + h] = m;
        }
    }
    __syncthreads();
    for (int i = tid; i < FF * GG; i += 256) {
        float m = fmaxf(fmaxf(s_pmax[0][i], s_pmax[1][i]), s_pmax[2][i]);
        s_conv[i] = fmaxf(m + b_conv[i], 0.0f);
    }
    __syncthreads();

    // Phase D: h(j) = relu(sum_i conv(i)*W1[i][j] + b1[j]); 2 indep chains
    if (tid < 240) {
        int j = tid % GG;
        int part = tid / GG;
        int i0 = part * 134;
        int i1 = (i0 + 134 < 400) ? (i0 + 134) : 400;
        float sa = 0.0f, sb = 0.0f;
        int i = i0;
        for (; i + 1 < i1; i += 2) {
            sa = fmaf(s_conv[i],     __ldg(W1 + (i)     * GG + j), sa);
            sb = fmaf(s_conv[i + 1], __ldg(W1 + (i + 1) * GG + j), sb);
        }
        if (i < i1) sa = fmaf(s_conv[i], __ldg(W1 + i * GG + j), sa);
        s_hp[part][j] = sa + sb;
    }
    __syncthreads();
    if (tid < GG) {
        float hv = s_hp[0][tid] + s_hp[1][tid] + s_hp[2][tid] + b1[tid];
        g_h[bp * GG + tid] = fmaxf(hv, 0.0f);
    }
}

// ---------------------------------------------------------------------------
// Kernel 2a: grid (slice s=0..7, batch b). cov slice (10 rows) + W2 partial.
// ---------------------------------------------------------------------------
__global__ void __launch_bounds__(256, 4)
masif_k2a(const float* __restrict__ W2)
{
    __shared__ float s_h[PP][GG];
    __shared__ float s_cov[800];
    __shared__ float s_red[4][64];

    const int tid = threadIdx.x;
    const int s = blockIdx.x;
    const int b = blockIdx.y;

    for (int i = tid; i < PP * GG; i += 256)
        s_h[i / GG][i % GG] = g_h[b * PP * GG + i];
    __syncthreads();

    for (int idx = tid; idx < 800; idx += 256) {
        int i1 = s * 10 + idx / GG;
        int i2 = idx % GG;
        float acc = 0.0f;
#pragma unroll
        for (int pp = 0; pp < PP; ++pp)
            acc = fmaf(s_h[pp][i1], s_h[pp][i2], acc);
        s_cov[idx] = acc * (1.0f / 32.0f);
    }
    __syncthreads();

    {
        const int j = tid % 64;
        const int part = tid / 64;
        const float* W2s = W2 + ((size_t)s * 800 + part * 200) * 64 + j;
        const float* cv = s_cov + part * 200;
        float a0 = 0.f, a1 = 0.f, a2 = 0.f, a3 = 0.f;
#pragma unroll 4
        for (int i = 0; i < 200; i += 4) {
            a0 = fmaf(cv[i + 0], __ldg(W2s + (size_t)(i + 0) * 64), a0);
            a1 = fmaf(cv[i + 1], __ldg(W2s + (size_t)(i + 1) * 64), a1);
            a2 = fmaf(cv[i + 2], __ldg(W2s + (size_t)(i + 2) * 64), a2);
            a3 = fmaf(cv[i + 3], __ldg(W2s + (size_t)(i + 3) * 64), a3);
        }
        s_red[part][j] = (a0 + a1) + (a2 + a3);
    }
    __syncthreads();
    if (tid < 64)
        g_p2[(b * 8 + s) * 64 + tid] =
            s_red[0][tid] + s_red[1][tid] + s_red[2][tid] + s_red[3][tid];
}

// ---------------------------------------------------------------------------
// Kernel 2b: one CTA per batch. reduce partials + relu + W3 + softmax.
// ---------------------------------------------------------------------------
__global__ void __launch_bounds__(64, 8)
masif_k2b(const float* __restrict__ b2,
          const float* __restrict__ W3, const float* __restrict__ b3,
          float* __restrict__ out)
{
    __shared__ float s_h2[64];
    __shared__ float s_logit[NLL];
    const int tid = threadIdx.x;
    const int b = blockIdx.x;

    {
        float v = b2[tid];
#pragma unroll
        for (int s = 0; s < 8; ++s)
            v += g_p2[(b * 8 + s) * 64 + tid];
        s_h2[tid] = fmaxf(v, 0.0f);
    }
    __syncthreads();
    if (tid < NLL) {
        float s = b3[tid];
#pragma unroll
        for (int j = 0; j < 64; ++j)
            s = fmaf(s_h2[j], W3[j * NLL + tid], s);
        s_logit[tid] = s;
    }
    __syncthreads();
    if (tid == 0) {
        float m = -INFINITY;
        for (int l = 0; l < NLL; ++l) m = fmaxf(m, s_logit[l]);
        float e[NLL];
        float sum = 0.0f;
        for (int l = 0; l < NLL; ++l) { e[l] = __expf(s_logit[l] - m); sum += e[l]; }
        float inv = 1.0f / sum;
        for (int l = 0; l < NLL; ++l) out[b * NLL + l] = e[l] * inv;
    }
}

extern "C" void kernel_launch(void* const* d_in, const int* in_sizes, int n_in,
                              void* d_out, int out_size)
{
    const float* x           = (const float*)d_in[0];
    const float* mu_rho      = (const float*)d_in[1];
    const float* sigma_rho   = (const float*)d_in[2];
    const float* mu_theta    = (const float*)d_in[3];
    const float* sigma_theta = (const float*)d_in[4];
    const float* W_conv      = (const float*)d_in[5];
    const float* b_conv      = (const float*)d_in[6];
    const float* W1          = (const float*)d_in[7];
    const float* b1          = (const float*)d_in[8];
    const float* W2          = (const float*)d_in[9];
    const float* b2          = (const float*)d_in[10];
    const float* W3          = (const float*)d_in[11];
    const float* b3          = (const float*)d_in[12];
    float* out = (float*)d_out;

    masif_k1<<<BBATCH * PP, 256>>>(x, mu_rho, sigma_rho, mu_theta, sigma_theta,
                                   W_conv, b_conv, W1, b1);
    masif_k2a<<<dim3(8, BBATCH), 256>>>(W2);
    masif_k2b<<<BBATCH, 64>>>(b2, W3, b3, out);
}